// round 7
// baseline (speedup 1.0000x reference)
#include <cuda_runtime.h>
#include <cuda_fp16.h>
#include <math.h>
#include <stdint.h>

#define T_TOK 16384
#define C_DIM 2048
#define E_NUM 64
#define NCH   32
#define NFMAX 4096
#define MARGIN 5e-4f

__device__ float g_ctx[4 * C_DIM];
__device__ float g_imp[E_NUM];
__device__ float g_load[E_NUM];
__device__ int   g_nflag;
__device__ int   g_flag[NFMAX];
__device__ __align__(16) __half g_gate[NCH][2][E_NUM][72];

#define APLANE  (128 * 144)
#define ABUF    (2 * APLANE)
#define BPLANE  (E_NUM * 144)
#define BBUF    (2 * BPLANE)
#define OFF_A   0
#define OFF_B   (2 * ABUF)
#define OFF_LOG (OFF_B + 4 * BBUF)
#define OFF_IMP (OFF_LOG + 128 * 65 * 4)
#define OFF_LD  (OFF_IMP + 256)
#define SMEMSZ  (OFF_LD + 256)

__device__ __forceinline__ uint32_t smem_u32(const void* p) {
    uint32_t a;
    asm("{ .reg .u64 t; cvta.to.shared.u64 t, %1; cvt.u32.u64 %0, t; }" : "=r"(a) : "l"(p));
    return a;
}
__device__ __forceinline__ void ldsm4(uint32_t* r, uint32_t a) {
    asm volatile("ldmatrix.sync.aligned.m8n8.x4.shared.b16 {%0,%1,%2,%3}, [%4];"
                 : "=r"(r[0]), "=r"(r[1]), "=r"(r[2]), "=r"(r[3]) : "r"(a));
}
__device__ __forceinline__ void mma(float* d, const uint32_t* a, const uint32_t* b) {
    asm volatile("mma.sync.aligned.m16n8k16.row.col.f32.f16.f16.f32 "
                 "{%0,%1,%2,%3}, {%4,%5,%6,%7}, {%8,%9}, {%0,%1,%2,%3};"
                 : "+f"(d[0]), "+f"(d[1]), "+f"(d[2]), "+f"(d[3])
                 : "r"(a[0]), "r"(a[1]), "r"(a[2]), "r"(a[3]), "r"(b[0]), "r"(b[1]));
}
__device__ __forceinline__ void cpa16(uint32_t dst, const void* src) {
    asm volatile("cp.async.cg.shared.global [%0], [%1], 16;" :: "r"(dst), "l"(src));
}
__device__ __forceinline__ uint32_t h2u(__half2 h) { return *(uint32_t*)&h; }

// ---------------------------------------------------------------------------
__global__ void __launch_bounds__(256) gate_conv_kernel(const float* __restrict__ gw)
{
    int idx = blockIdx.x * 256 + threadIdx.x;
    int e  = idx >> 10;
    int k0 = (idx & 1023) << 1;
    int c  = k0 >> 6, col = k0 & 63;
    float v0 = gw[(size_t)e * C_DIM + k0];
    float v1 = gw[(size_t)e * C_DIM + k0 + 1];
    __half2 m = __floats2half2_rn(v0, v1);
    float2 mb = __half22float2(m);
    __half2 r = __floats2half2_rn((v0 - mb.x) * 4096.f, (v1 - mb.y) * 4096.f);
    *(__half2*)&g_gate[c][0][e][col] = m;
    *(__half2*)&g_gate[c][1][e][col] = r;
}

// ---------------------------------------------------------------------------
// ctx: bitwise-identical arithmetic to the R3 kernel (same per-lane fmaf
// chains, same shfl tree).  Only the LOADS are batched (pure, value-safe).
// ---------------------------------------------------------------------------
__global__ void __launch_bounds__(256) ctx_kernel(const float* __restrict__ rc,
                                                  const float* __restrict__ ctx_w)
{
    if (blockIdx.x == 0 && threadIdx.x < 2 * E_NUM) {
        if (threadIdx.x < E_NUM) g_imp[threadIdx.x] = 0.f;
        else                     g_load[threadIdx.x - E_NUM] = 0.f;
        if (threadIdx.x == 0)    g_nflag = 0;
    }
    const int c    = blockIdx.x * 8 + (threadIdx.x >> 5);
    const int lane = threadIdx.x & 31;
    const float4* w4  = (const float4*)(ctx_w + (size_t)c * C_DIM) + lane;
    const float4* r0p = (const float4*)(rc)             + lane;
    const float4* r1p = (const float4*)(rc +     C_DIM) + lane;
    const float4* r2p = (const float4*)(rc + 2 * C_DIM) + lane;
    const float4* r3p = (const float4*)(rc + 3 * C_DIM) + lane;
    float a0 = 0.f, a1 = 0.f, a2 = 0.f, a3 = 0.f;
    #pragma unroll
    for (int half = 0; half < 2; half++) {
        float4 wv[8];
        #pragma unroll
        for (int j = 0; j < 8; j++) wv[j] = w4[(half * 8 + j) * 32];
        #pragma unroll
        for (int j = 0; j < 8; j++) {
            int jj = half * 8 + j;
            float4 q0 = r0p[jj * 32], q1 = r1p[jj * 32];
            float4 q2 = r2p[jj * 32], q3 = r3p[jj * 32];
            float4 w = wv[j];
            a0 = fmaf(w.x, q0.x, fmaf(w.y, q0.y, fmaf(w.z, q0.z, fmaf(w.w, q0.w, a0))));
            a1 = fmaf(w.x, q1.x, fmaf(w.y, q1.y, fmaf(w.z, q1.z, fmaf(w.w, q1.w, a1))));
            a2 = fmaf(w.x, q2.x, fmaf(w.y, q2.y, fmaf(w.z, q2.z, fmaf(w.w, q2.w, a2))));
            a3 = fmaf(w.x, q3.x, fmaf(w.y, q3.y, fmaf(w.z, q3.z, fmaf(w.w, q3.w, a3))));
        }
    }
    #pragma unroll
    for (int o = 16; o; o >>= 1) {
        a0 += __shfl_down_sync(0xffffffffu, a0, o);
        a1 += __shfl_down_sync(0xffffffffu, a1, o);
        a2 += __shfl_down_sync(0xffffffffu, a2, o);
        a3 += __shfl_down_sync(0xffffffffu, a3, o);
    }
    if (lane == 0) {
        g_ctx[c]             = a0;
        g_ctx[C_DIM + c]     = a1;
        g_ctx[2 * C_DIM + c] = a2;
        g_ctx[3 * C_DIM + c] = a3;
    }
}

// ---------------------------------------------------------------------------
// Router: fp16 2-split emulated-fp32 GEMM via mma.sync (R6 machinery) +
// fused epilogue.  Low-margin tokens are flagged for exact fixup.
// ---------------------------------------------------------------------------
__global__ void __launch_bounds__(256, 1) router_kernel(const float* __restrict__ x,
                                                        float* __restrict__ out)
{
    extern __shared__ unsigned char smem[];
    const int tid    = threadIdx.x;
    const int wid    = tid >> 5;
    const int lane   = tid & 31;
    const int token0 = blockIdx.x * 128;
    const int batch  = token0 >> 12;
    const uint32_t sb = smem_u32(smem);

    float* sLog  = (float*)(smem + OFF_LOG);
    float* sImp  = (float*)(smem + OFF_IMP);
    int*   sLoad = (int*)(smem + OFF_LD);
    if (tid < E_NUM) { sImp[tid] = 0.f; sLoad[tid] = 0; }

    const int lrow = tid >> 1, lh = tid & 1;
    const float* xrow = x + (size_t)(token0 + lrow) * C_DIM + lh * 32;
    const float* crow = g_ctx + (size_t)batch * C_DIM + lh * 32;

    const uint32_t aoff = (uint32_t)((wid * 16 + (lane & 15)) * 144 + (lane >> 4) * 16);
    const uint32_t boff = (uint32_t)(((lane & 7) + ((lane >> 4) << 3)) * 144 + ((lane >> 3) & 1) * 16);

    float Dm[8][4], Dc[8][4];
    #pragma unroll
    for (int f = 0; f < 8; f++)
        #pragma unroll
        for (int i = 0; i < 4; i++) { Dm[f][i] = 0.f; Dc[f][i] = 0.f; }

    #pragma unroll
    for (int cc = 0; cc < 2; cc++) {
        const unsigned char* src = (const unsigned char*)g_gate[cc];
        #pragma unroll
        for (int j = 0; j < 5; j++) {
            int q = tid + j * 256;
            if (q < BBUF / 16) cpa16(sb + OFF_B + cc * BBUF + q * 16, src + q * 16);
        }
        asm volatile("cp.async.commit_group;" ::: "memory");
    }
    float4 xr[8];
    #pragma unroll
    for (int j = 0; j < 8; j++) xr[j] = ((const float4*)xrow)[j];

    for (int c = 0; c < NCH; c++) {
        const int ba = c & 1, bb = c & 3;
        if (c + 2 < NCH) {
            const unsigned char* src = (const unsigned char*)g_gate[c + 2];
            #pragma unroll
            for (int j = 0; j < 5; j++) {
                int q = tid + j * 256;
                if (q < BBUF / 16) cpa16(sb + OFF_B + ((c + 2) & 3) * BBUF + q * 16, src + q * 16);
            }
            asm volatile("cp.async.commit_group;" ::: "memory");
            asm volatile("cp.async.wait_group 2;" ::: "memory");
        } else {
            asm volatile("cp.async.wait_group 0;" ::: "memory");
        }
        {
            unsigned char* A0 = smem + OFF_A + ba * ABUF;
            unsigned char* A1 = A0 + APLANE;
            const float4* cp4 = (const float4*)(crow + c * 64);
            uint32_t rb = (uint32_t)(lrow * 144 + lh * 64);
            #pragma unroll
            for (int j = 0; j < 8; j++) {
                float4 v = xr[j], cv = cp4[j];
                v.x += cv.x; v.y += cv.y; v.z += cv.z; v.w += cv.w;
                __half2 m0 = __floats2half2_rn(v.x, v.y);
                __half2 m1 = __floats2half2_rn(v.z, v.w);
                float2 b0 = __half22float2(m0), b1 = __half22float2(m1);
                __half2 r0 = __floats2half2_rn((v.x - b0.x) * 4096.f, (v.y - b0.y) * 4096.f);
                __half2 r1 = __floats2half2_rn((v.z - b1.x) * 4096.f, (v.w - b1.y) * 4096.f);
                *(uint2*)(A0 + rb + j * 8) = make_uint2(h2u(m0), h2u(m1));
                *(uint2*)(A1 + rb + j * 8) = make_uint2(h2u(r0), h2u(r1));
            }
        }
        if (c + 1 < NCH) {
            const float4* nx = (const float4*)(xrow + (c + 1) * 64);
            #pragma unroll
            for (int j = 0; j < 8; j++) xr[j] = nx[j];
        }
        __syncthreads();
        const uint32_t a0b = sb + OFF_A + ba * ABUF + aoff;
        const uint32_t a1b = a0b + APLANE;
        const uint32_t b0b = sb + OFF_B + bb * BBUF + boff;
        const uint32_t b1b = b0b + BPLANE;
        #pragma unroll
        for (int ks = 0; ks < 4; ks++) {
            uint32_t A0[4], A1[4], B0[16], B1[16];
            ldsm4(A0, a0b + ks * 32);
            ldsm4(A1, a1b + ks * 32);
            #pragma unroll
            for (int g = 0; g < 4; g++) {
                ldsm4(B0 + 4 * g, b0b + ks * 32 + g * 16 * 144);
                ldsm4(B1 + 4 * g, b1b + ks * 32 + g * 16 * 144);
            }
            #pragma unroll
            for (int f = 0; f < 8; f++) {
                mma(Dm[f], A0, B0 + f * 2);
                mma(Dc[f], A0, B1 + f * 2);
                mma(Dc[f], A1, B0 + f * 2);
            }
        }
    }

    #pragma unroll
    for (int f = 0; f < 8; f++)
        #pragma unroll
        for (int i = 0; i < 4; i++) {
            int row = (lane >> 2) + 8 * (i >> 1);
            int col = f * 8 + 2 * (lane & 3) + (i & 1);
            sLog[(wid * 16 + row) * 65 + col] = Dm[f][i] + Dc[f][i] * 2.44140625e-4f;
        }
    __syncthreads();

    if (tid < 128) {
        const int tok = token0 + tid;
        float* row = &sLog[tid * 65];
        float v0 = -1e30f, v1 = -1e30f, v2 = -1e30f;
        int   i0 = 0, i1 = 0;
        for (int e = 0; e < E_NUM; e++) {
            float l = row[e];
            if (l > v0)      { v2 = v1; v1 = v0; i1 = i0; v0 = l; i0 = e; }
            else if (l > v1) { v2 = v1; v1 = l; i1 = e; }
            else if (l > v2) { v2 = l; }
        }
        // flag low-margin tokens for exact (bitwise-R3) recomputation
        if (v0 - v1 < MARGIN || v1 - v2 < MARGIN) {
            int s = atomicAdd(&g_nflag, 1);
            if (s < NFMAX) g_flag[s] = tok;
        }
        float sum = 0.f;
        for (int e = 0; e < E_NUM; e++) {
            float p = expf(row[e] - v0);
            row[e] = p;
            sum += p;
        }
        float inv = 1.0f / sum;
        int ln = tid & 31;
        for (int e = 0; e < E_NUM; e++) {
            int ee = (e + ln) & 63;
            atomicAdd(&sImp[ee], row[ee] * inv);
        }
        atomicAdd(&sLoad[i0], 1);
        atomicAdd(&sLoad[i1], 1);
        float e1 = expf(v1 - v0);
        float w0 = 1.0f / (1.0f + e1);
        out[(size_t)tok * 2 + 0] = (float)i0;
        out[(size_t)tok * 2 + 1] = (float)i1;
        out[2 * T_TOK + (size_t)tok * 2 + 0] = w0;
        out[2 * T_TOK + (size_t)tok * 2 + 1] = e1 * w0;
    }
    __syncthreads();
    if (tid < E_NUM) {
        atomicAdd(&g_imp[tid],  sImp[tid]);
        atomicAdd(&g_load[tid], (float)sLoad[tid]);
    }
}

// ---------------------------------------------------------------------------
// Fixup: flagged tokens get logits recomputed with the EXACT chain of the
// known-passing R3 kernel: acc = fmaf(rn(x_k + ctx_k), w_k, acc), k ascending,
// single fp32 accumulator per (token, expert).  Bitwise-identical results.
// ---------------------------------------------------------------------------
__global__ void __launch_bounds__(64) fixup_kernel(const float* __restrict__ x,
                                                   const float* __restrict__ gate_w,
                                                   float* __restrict__ out)
{
    __shared__ float sv[E_NUM];
    int nf = g_nflag;
    if (nf > NFMAX) nf = NFMAX;
    for (int it = blockIdx.x; it < nf; it += gridDim.x) {
        const int tok   = g_flag[it];
        const int batch = tok >> 12;
        const float* xr = x + (size_t)tok * C_DIM;
        const float* cr = g_ctx + (size_t)batch * C_DIM;
        const int e = threadIdx.x;
        const float* w = gate_w + (size_t)e * C_DIM;
        float acc = 0.f;
        for (int k = 0; k < C_DIM; k += 4) {
            float4 xv = *(const float4*)(xr + k);
            float4 cv = *(const float4*)(cr + k);
            float4 wv = *(const float4*)(w + k);
            acc = fmaf(xv.x + cv.x, wv.x, acc);
            acc = fmaf(xv.y + cv.y, wv.y, acc);
            acc = fmaf(xv.z + cv.z, wv.z, acc);
            acc = fmaf(xv.w + cv.w, wv.w, acc);
        }
        sv[e] = acc;
        __syncthreads();
        if (e == 0) {
            float v0 = -1e30f, v1 = -1e30f;
            int   i0 = 0, i1 = 0;
            for (int q = 0; q < E_NUM; q++) {
                float l = sv[q];
                if (l > v0)      { v1 = v0; i1 = i0; v0 = l; i0 = q; }
                else if (l > v1) { v1 = l; i1 = q; }
            }
            int o0 = (int)out[(size_t)tok * 2], o1 = (int)out[(size_t)tok * 2 + 1];
            if (o0 != i0 || o1 != i1) {
                atomicAdd(&g_load[o0], -1.f);
                atomicAdd(&g_load[o1], -1.f);
                atomicAdd(&g_load[i0],  1.f);
                atomicAdd(&g_load[i1],  1.f);
            }
            float e1 = expf(v1 - v0);
            float w0 = 1.0f / (1.0f + e1);
            out[(size_t)tok * 2 + 0] = (float)i0;
            out[(size_t)tok * 2 + 1] = (float)i1;
            out[2 * T_TOK + (size_t)tok * 2 + 0] = w0;
            out[2 * T_TOK + (size_t)tok * 2 + 1] = e1 * w0;
        }
        __syncthreads();
    }
}

// ---------------------------------------------------------------------------
__global__ void aux_kernel(float* __restrict__ out)
{
    __shared__ float s[E_NUM];
    int t = threadIdx.x;
    s[t] = g_imp[t] * g_load[t];
    __syncthreads();
    if (t == 0) {
        float a = 0.f;
        for (int e = 0; e < E_NUM; e++) a += s[e];
        out[4 * T_TOK] = (float)E_NUM * a / ((float)T_TOK * (float)T_TOK);
    }
}

// ---------------------------------------------------------------------------
extern "C" void kernel_launch(void* const* d_in, const int* in_sizes, int n_in,
                              void* d_out, int out_size)
{
    const float* x      = (const float*)d_in[0];
    const float* rc     = (const float*)d_in[1];
    const float* gate_w = (const float*)d_in[2];
    const float* ctx_w  = (const float*)d_in[3];
    float* out = (float*)d_out;

    cudaFuncSetAttribute(router_kernel, cudaFuncAttributeMaxDynamicSharedMemorySize, SMEMSZ);

    gate_conv_kernel<<<256, 256>>>(gate_w);
    ctx_kernel      <<<256, 256>>>(rc, ctx_w);
    router_kernel   <<<128, 256, SMEMSZ>>>(x, out);
    fixup_kernel    <<<128, 64>>>(x, gate_w, out);
    aux_kernel      <<<1, E_NUM>>>(out);
}

// round 8
// speedup vs baseline: 1.3594x; 1.3594x over previous
#include <cuda_runtime.h>
#include <math.h>

#define T_TOK 16384
#define C_DIM 2048
#define E_NUM 64

__device__ float g_ctx[4 * C_DIM];      // (4, 2048)  context projection
__device__ float g_imp[E_NUM];
__device__ float g_load[E_NUM];

// packed f32x2 FMA: d = a * b + d  (two IEEE fp32 FMAs, one instruction)
__device__ __forceinline__ void ffma2(unsigned long long& d,
                                      unsigned long long a,
                                      unsigned long long b)
{
    asm("fma.rn.f32x2 %0, %1, %2, %0;" : "+l"(d) : "l"(a), "l"(b));
}
__device__ __forceinline__ unsigned long long pack2(float v)
{
    unsigned long long r;
    unsigned int u = __float_as_uint(v);
    asm("mov.b64 %0, {%1, %1};" : "=l"(r) : "r"(u));
    return r;
}

// ---------------------------------------------------------------------------
// Kernel 1: ctx[b][c] = sum_k rc[b][k] * ctx_w[c][k]
// One warp per column (2048 warps).  Arithmetic chain is bitwise-identical to
// the R3 kernel; only the ctx_w LOADS are batched up-front (16 lines in
// flight per warp) to saturate HBM instead of being latency-bound.
// ---------------------------------------------------------------------------
__global__ void __launch_bounds__(256) ctx_kernel(const float* __restrict__ rc,
                                                  const float* __restrict__ ctx_w)
{
    if (blockIdx.x == 0 && threadIdx.x < 2 * E_NUM) {
        if (threadIdx.x < E_NUM) g_imp[threadIdx.x] = 0.f;
        else                     g_load[threadIdx.x - E_NUM] = 0.f;
    }
    const int c    = blockIdx.x * 8 + (threadIdx.x >> 5);
    const int lane = threadIdx.x & 31;

    const float4* w4  = (const float4*)(ctx_w + (size_t)c * C_DIM) + lane;
    const float4* r0p = (const float4*)(rc)             + lane;
    const float4* r1p = (const float4*)(rc +     C_DIM) + lane;
    const float4* r2p = (const float4*)(rc + 2 * C_DIM) + lane;
    const float4* r3p = (const float4*)(rc + 3 * C_DIM) + lane;

    float4 wv[16];
    #pragma unroll
    for (int j = 0; j < 16; j++) wv[j] = w4[j * 32];   // 16 DRAM lines in flight

    float a0 = 0.f, a1 = 0.f, a2 = 0.f, a3 = 0.f;
    #pragma unroll
    for (int j = 0; j < 16; j++) {
        float4 q0 = r0p[j * 32], q1 = r1p[j * 32];
        float4 q2 = r2p[j * 32], q3 = r3p[j * 32];
        float4 w = wv[j];
        a0 = fmaf(w.x, q0.x, fmaf(w.y, q0.y, fmaf(w.z, q0.z, fmaf(w.w, q0.w, a0))));
        a1 = fmaf(w.x, q1.x, fmaf(w.y, q1.y, fmaf(w.z, q1.z, fmaf(w.w, q1.w, a1))));
        a2 = fmaf(w.x, q2.x, fmaf(w.y, q2.y, fmaf(w.z, q2.z, fmaf(w.w, q2.w, a2))));
        a3 = fmaf(w.x, q3.x, fmaf(w.y, q3.y, fmaf(w.z, q3.z, fmaf(w.w, q3.w, a3))));
    }
    #pragma unroll
    for (int o = 16; o; o >>= 1) {
        a0 += __shfl_down_sync(0xffffffffu, a0, o);
        a1 += __shfl_down_sync(0xffffffffu, a1, o);
        a2 += __shfl_down_sync(0xffffffffu, a2, o);
        a3 += __shfl_down_sync(0xffffffffu, a3, o);
    }
    if (lane == 0) {
        g_ctx[c]             = a0;
        g_ctx[C_DIM + c]     = a1;
        g_ctx[2 * C_DIM + c] = a2;
        g_ctx[3 * C_DIM + c] = a3;
    }
}

// ---------------------------------------------------------------------------
// Kernel 2: logits = (x + ctx) @ gate_w.T + fused router epilogue.
// BM=64 tokens per CTA, 256 CTAs (2 CTAs/SM, single wave on 148 SMs).
// Per-(token,expert) arithmetic is the identical FFMA2 chain of the passing
// R3 kernel (same chunk order, same kk order, same f32x2 pairing), so the
// outputs are bitwise-identical to R3; only the work partitioning changed.
// Thread micro-tile: 2 tokens x 8 experts.
// ---------------------------------------------------------------------------
__global__ void __launch_bounds__(256) router_kernel(const float* __restrict__ x,
                                                     const float* __restrict__ gate_w,
                                                     float* __restrict__ out)
{
    __shared__ float xs[16 * 64];      // xs[k][token]  (k-major)
    __shared__ float gs[16 * 64];      // gs[k][expert]
    __shared__ float sLog[64 * 65];    // padded logits rows
    __shared__ float sImp[E_NUM];
    __shared__ int   sLoad[E_NUM];

    const int tid    = threadIdx.x;
    const int token0 = blockIdx.x * 64;
    const int batch  = token0 >> 12;   // 64 | 4096

    // loader mapping: tid -> (row lt, k-quad lk); lt covers 64 tokens AND 64 experts
    const int lt = tid >> 2;
    const int lk = (tid & 3) << 2;
    const float4* xp = (const float4*)(x      + (size_t)(token0 + lt) * C_DIM + lk);
    const float4* gp = (const float4*)(gate_w + (size_t)lt             * C_DIM + lk);
    const float4* cp = (const float4*)(g_ctx  + (size_t)batch          * C_DIM + lk);

    // compute mapping: tid -> (token base ti, expert base ej)
    const int ti = (tid & 31) << 1;   // 0..62 step 2
    const int ej = (tid >> 5) << 3;   // 0..56 step 8

    unsigned long long acc2[2][4];
    #pragma unroll
    for (int a = 0; a < 2; a++)
        #pragma unroll
        for (int b = 0; b < 4; b++) acc2[a][b] = 0ull;

    float4 ra = *xp, rg = *gp, rc = *cp;

    for (int kc = 0; kc < 128; kc++) {
        #pragma unroll
        for (int i = 0; i < 4; i++) {
            xs[(lk + i) * 64 + lt] = ((const float*)&ra)[i] + ((const float*)&rc)[i];
            gs[(lk + i) * 64 + lt] = ((const float*)&rg)[i];
        }
        __syncthreads();
        if (kc < 127) {
            ra = xp[(kc + 1) * 4];
            rg = gp[(kc + 1) * 4];
            rc = cp[(kc + 1) * 4];
        }
        #pragma unroll
        for (int kk = 0; kk < 16; kk++) {
            float2 xv = *(const float2*)&xs[kk * 64 + ti];
            ulonglong2 gA = *(const ulonglong2*)&gs[kk * 64 + ej];
            ulonglong2 gB = *(const ulonglong2*)&gs[kk * 64 + ej + 4];
            unsigned long long xp0 = pack2(xv.x), xp1 = pack2(xv.y);
            ffma2(acc2[0][0], xp0, gA.x);
            ffma2(acc2[0][1], xp0, gA.y);
            ffma2(acc2[0][2], xp0, gB.x);
            ffma2(acc2[0][3], xp0, gB.y);
            ffma2(acc2[1][0], xp1, gA.x);
            ffma2(acc2[1][1], xp1, gA.y);
            ffma2(acc2[1][2], xp1, gB.x);
            ffma2(acc2[1][3], xp1, gB.y);
        }
        __syncthreads();
    }

    if (tid < E_NUM) { sImp[tid] = 0.f; sLoad[tid] = 0; }
    #pragma unroll
    for (int a = 0; a < 2; a++)
        #pragma unroll
        for (int b = 0; b < 4; b++) {
            unsigned int lo, hi;
            asm("mov.b64 {%0, %1}, %2;" : "=r"(lo), "=r"(hi) : "l"(acc2[a][b]));
            sLog[(ti + a) * 65 + ej + 2 * b]     = __uint_as_float(lo);
            sLog[(ti + a) * 65 + ej + 2 * b + 1] = __uint_as_float(hi);
        }
    __syncthreads();

    // -------- fused epilogue: one thread per token --------
    if (tid < 64) {
        const int tok = token0 + tid;
        float* row = &sLog[tid * 65];

        float v0 = -1e30f, v1 = -1e30f;
        int   i0 = 0, i1 = 0;
        for (int e = 0; e < E_NUM; e++) {
            float l = row[e];
            if (l > v0)      { v1 = v0; i1 = i0; v0 = l; i0 = e; }
            else if (l > v1) { v1 = l; i1 = e; }
        }
        float sum = 0.f;
        for (int e = 0; e < E_NUM; e++) {
            float p = expf(row[e] - v0);
            row[e] = p;
            sum += p;
        }
        float inv = 1.0f / sum;
        int lane = tid & 31;
        for (int e = 0; e < E_NUM; e++) {
            int ee = (e + lane) & 63;
            atomicAdd(&sImp[ee], row[ee] * inv);
        }
        atomicAdd(&sLoad[i0], 1);
        atomicAdd(&sLoad[i1], 1);

        float e1 = expf(v1 - v0);
        float w0 = 1.0f / (1.0f + e1);
        out[(size_t)tok * 2 + 0] = (float)i0;
        out[(size_t)tok * 2 + 1] = (float)i1;
        out[2 * T_TOK + (size_t)tok * 2 + 0] = w0;
        out[2 * T_TOK + (size_t)tok * 2 + 1] = e1 * w0;
    }
    __syncthreads();
    if (tid < E_NUM) {
        atomicAdd(&g_imp[tid],  sImp[tid]);
        atomicAdd(&g_load[tid], (float)sLoad[tid]);
    }
}

// ---------------------------------------------------------------------------
__global__ void aux_kernel(float* __restrict__ out)
{
    __shared__ float s[E_NUM];
    int t = threadIdx.x;
    s[t] = g_imp[t] * g_load[t];
    __syncthreads();
    if (t == 0) {
        float a = 0.f;
        for (int e = 0; e < E_NUM; e++) a += s[e];
        out[4 * T_TOK] = (float)E_NUM * a / ((float)T_TOK * (float)T_TOK);
    }
}

// ---------------------------------------------------------------------------
extern "C" void kernel_launch(void* const* d_in, const int* in_sizes, int n_in,
                              void* d_out, int out_size)
{
    const float* x      = (const float*)d_in[0];
    const float* rc     = (const float*)d_in[1];
    const float* gate_w = (const float*)d_in[2];
    const float* ctx_w  = (const float*)d_in[3];
    float* out = (float*)d_out;

    ctx_kernel   <<<256, 256>>>(rc, ctx_w);
    router_kernel<<<256, 256>>>(x, gate_w, out);
    aux_kernel   <<<1, E_NUM>>>(out);
}

// round 9
// speedup vs baseline: 2.2562x; 1.6597x over previous
#include <cuda_runtime.h>
#include <math.h>

#define T_TOK 16384
#define C_DIM 2048
#define E_NUM 64

__device__ float g_ctx[4 * C_DIM];
__device__ float g_imp[E_NUM];
__device__ float g_load[E_NUM];

__device__ __forceinline__ void ffma2(unsigned long long& d,
                                      unsigned long long a,
                                      unsigned long long b)
{
    asm("fma.rn.f32x2 %0, %1, %2, %0;" : "+l"(d) : "l"(a), "l"(b));
}
__device__ __forceinline__ unsigned long long pack2(float v)
{
    unsigned long long r;
    unsigned int u = __float_as_uint(v);
    asm("mov.b64 %0, {%1, %1};" : "=l"(r) : "r"(u));
    return r;
}

// ---------------------------------------------------------------------------
// ctx[b][c] = sum_k rc[b][k] * ctx_w[c][k]  — bitwise-R3 chain (proven).
// ---------------------------------------------------------------------------
__global__ void __launch_bounds__(256) ctx_kernel(const float* __restrict__ rc,
                                                  const float* __restrict__ ctx_w)
{
    if (blockIdx.x == 0 && threadIdx.x < 2 * E_NUM) {
        if (threadIdx.x < E_NUM) g_imp[threadIdx.x] = 0.f;
        else                     g_load[threadIdx.x - E_NUM] = 0.f;
    }
    const int c    = blockIdx.x * 8 + (threadIdx.x >> 5);
    const int lane = threadIdx.x & 31;

    const float4* w4  = (const float4*)(ctx_w + (size_t)c * C_DIM) + lane;
    const float4* r0p = (const float4*)(rc)             + lane;
    const float4* r1p = (const float4*)(rc +     C_DIM) + lane;
    const float4* r2p = (const float4*)(rc + 2 * C_DIM) + lane;
    const float4* r3p = (const float4*)(rc + 3 * C_DIM) + lane;

    float4 wv[16];
    #pragma unroll
    for (int j = 0; j < 16; j++) wv[j] = w4[j * 32];

    float a0 = 0.f, a1 = 0.f, a2 = 0.f, a3 = 0.f;
    #pragma unroll
    for (int j = 0; j < 16; j++) {
        float4 q0 = r0p[j * 32], q1 = r1p[j * 32];
        float4 q2 = r2p[j * 32], q3 = r3p[j * 32];
        float4 w = wv[j];
        a0 = fmaf(w.x, q0.x, fmaf(w.y, q0.y, fmaf(w.z, q0.z, fmaf(w.w, q0.w, a0))));
        a1 = fmaf(w.x, q1.x, fmaf(w.y, q1.y, fmaf(w.z, q1.z, fmaf(w.w, q1.w, a1))));
        a2 = fmaf(w.x, q2.x, fmaf(w.y, q2.y, fmaf(w.z, q2.z, fmaf(w.w, q2.w, a2))));
        a3 = fmaf(w.x, q3.x, fmaf(w.y, q3.y, fmaf(w.z, q3.z, fmaf(w.w, q3.w, a3))));
    }
    #pragma unroll
    for (int o = 16; o; o >>= 1) {
        a0 += __shfl_down_sync(0xffffffffu, a0, o);
        a1 += __shfl_down_sync(0xffffffffu, a1, o);
        a2 += __shfl_down_sync(0xffffffffu, a2, o);
        a3 += __shfl_down_sync(0xffffffffu, a3, o);
    }
    if (lane == 0) {
        g_ctx[c]             = a0;
        g_ctx[C_DIM + c]     = a1;
        g_ctx[2 * C_DIM + c] = a2;
        g_ctx[3 * C_DIM + c] = a3;
    }
}

// ---------------------------------------------------------------------------
// Router: logits = (x + ctx) @ gate_w.T + fused epilogue.
// R3 compute structure (BM=128, 4 tok x 8 exp per thread, grid 128) with
// BK=32 double-buffered smem and ONE __syncthreads per K-chunk (64 barriers
// vs R3's 256).  k ascends identically per accumulator -> bitwise-R3 output.
// Dynamic smem layout:
//   [0]      xs: 2 x 32 x 128 f32   (32 KB)
//   [32768]  gs: 2 x 32 x 64  f32   (16 KB)
//   [49152]  sLog: 128 x 65 f32     (33.3 KB)
//   [82432]  sImp (64 f32), [82688] sLoad (64 int)
// ---------------------------------------------------------------------------
#define OFF_XS  0
#define OFF_GS  32768
#define OFF_LOG 49152
#define OFF_IMP 82432
#define OFF_LD  82688
#define SMEMSZ  82944

__global__ void __launch_bounds__(256, 1) router_kernel(const float* __restrict__ x,
                                                        const float* __restrict__ gate_w,
                                                        float* __restrict__ out)
{
    extern __shared__ unsigned char smem[];
    float* xs2   = (float*)(smem + OFF_XS);     // [buf][k][token]
    float* gs2   = (float*)(smem + OFF_GS);     // [buf][k][expert]
    float* sLog  = (float*)(smem + OFF_LOG);
    float* sImp  = (float*)(smem + OFF_IMP);
    int*   sLoad = (int*)(smem + OFF_LD);

    const int tid    = threadIdx.x;
    const int token0 = blockIdx.x * 128;
    const int batch  = token0 >> 12;

    if (tid < E_NUM) { sImp[tid] = 0.f; sLoad[tid] = 0; }

    // loader mapping (BK=32):
    //  x/ctx: 2 threads per token row, 16 floats (4 float4) each
    const int lt = tid >> 1;            // 0..127
    const int lh = (tid & 1) << 4;      // 0 or 16
    //  gate : 4 threads per expert row, 8 floats (2 float4) each
    const int ge = tid >> 2;            // 0..63
    const int gk = (tid & 3) << 3;      // 0,8,16,24
    const float4* xp = (const float4*)(x      + (size_t)(token0 + lt) * C_DIM + lh);
    const float4* cp = (const float4*)(g_ctx  + (size_t)batch         * C_DIM + lh);
    const float4* gp = (const float4*)(gate_w + (size_t)ge            * C_DIM + gk);

    // compute mapping: tid -> (token base ti, expert base ej)
    const int ti = (tid & 31) << 2;     // 0..124 step 4
    const int ej = (tid >> 5) << 3;     // 0..56  step 8

    unsigned long long acc2[4][4];
    #pragma unroll
    for (int a = 0; a < 4; a++)
        #pragma unroll
        for (int b = 0; b < 4; b++) acc2[a][b] = 0ull;

    // prologue: load chunk 0, stage into buffer 0
    float4 xr[4], cr[4], gr[2];
    #pragma unroll
    for (int j = 0; j < 4; j++) { xr[j] = xp[j]; cr[j] = cp[j]; }
    #pragma unroll
    for (int j = 0; j < 2; j++) gr[j] = gp[j];
    {
        float* xs = xs2;
        float* gs = gs2;
        #pragma unroll
        for (int j = 0; j < 4; j++)
            #pragma unroll
            for (int i = 0; i < 4; i++)
                xs[(lh + j * 4 + i) * 128 + lt] = ((const float*)&xr[j])[i] + ((const float*)&cr[j])[i];
        #pragma unroll
        for (int j = 0; j < 2; j++)
            #pragma unroll
            for (int i = 0; i < 4; i++)
                gs[(gk + j * 4 + i) * 64 + ge] = ((const float*)&gr[j])[i];
    }
    __syncthreads();

    for (int c = 0; c < 64; c++) {
        // prefetch chunk c+1 (hidden behind the compute block)
        if (c < 63) {
            #pragma unroll
            for (int j = 0; j < 4; j++) {
                xr[j] = xp[(c + 1) * 8 + j];
                cr[j] = cp[(c + 1) * 8 + j];
            }
            #pragma unroll
            for (int j = 0; j < 2; j++) gr[j] = gp[(c + 1) * 8 + j];
        }
        // compute chunk c from buffer c&1 (identical FFMA2 chain to R3)
        const float* xs = xs2 + (c & 1) * (32 * 128);
        const float* gs = gs2 + (c & 1) * (32 * 64);
        #pragma unroll
        for (int kk = 0; kk < 32; kk++) {
            float4 xv = *(const float4*)&xs[kk * 128 + ti];
            ulonglong2 gA = *(const ulonglong2*)&gs[kk * 64 + ej];
            ulonglong2 gB = *(const ulonglong2*)&gs[kk * 64 + ej + 4];
            unsigned long long xq[4] = {pack2(xv.x), pack2(xv.y), pack2(xv.z), pack2(xv.w)};
            #pragma unroll
            for (int a = 0; a < 4; a++) {
                ffma2(acc2[a][0], xq[a], gA.x);
                ffma2(acc2[a][1], xq[a], gA.y);
                ffma2(acc2[a][2], xq[a], gB.x);
                ffma2(acc2[a][3], xq[a], gB.y);
            }
        }
        // stage chunk c+1 into the other buffer
        if (c < 63) {
            float* xsn = xs2 + ((c + 1) & 1) * (32 * 128);
            float* gsn = gs2 + ((c + 1) & 1) * (32 * 64);
            #pragma unroll
            for (int j = 0; j < 4; j++)
                #pragma unroll
                for (int i = 0; i < 4; i++)
                    xsn[(lh + j * 4 + i) * 128 + lt] = ((const float*)&xr[j])[i] + ((const float*)&cr[j])[i];
            #pragma unroll
            for (int j = 0; j < 2; j++)
                #pragma unroll
                for (int i = 0; i < 4; i++)
                    gsn[(gk + j * 4 + i) * 64 + ge] = ((const float*)&gr[j])[i];
        }
        __syncthreads();
    }

    // spill logits (padded rows)
    #pragma unroll
    for (int a = 0; a < 4; a++)
        #pragma unroll
        for (int b = 0; b < 4; b++) {
            unsigned int lo, hi;
            asm("mov.b64 {%0, %1}, %2;" : "=r"(lo), "=r"(hi) : "l"(acc2[a][b]));
            sLog[(ti + a) * 65 + ej + 2 * b]     = __uint_as_float(lo);
            sLog[(ti + a) * 65 + ej + 2 * b + 1] = __uint_as_float(hi);
        }
    __syncthreads();

    // fused epilogue: one thread per token (unchanged from R3)
    if (tid < 128) {
        const int tok = token0 + tid;
        float* row = &sLog[tid * 65];

        float v0 = -1e30f, v1 = -1e30f;
        int   i0 = 0, i1 = 0;
        for (int e = 0; e < E_NUM; e++) {
            float l = row[e];
            if (l > v0)      { v1 = v0; i1 = i0; v0 = l; i0 = e; }
            else if (l > v1) { v1 = l; i1 = e; }
        }
        float sum = 0.f;
        for (int e = 0; e < E_NUM; e++) {
            float p = expf(row[e] - v0);
            row[e] = p;
            sum += p;
        }
        float inv = 1.0f / sum;
        int lane = tid & 31;
        for (int e = 0; e < E_NUM; e++) {
            int ee = (e + lane) & 63;
            atomicAdd(&sImp[ee], row[ee] * inv);
        }
        atomicAdd(&sLoad[i0], 1);
        atomicAdd(&sLoad[i1], 1);

        float e1 = expf(v1 - v0);
        float w0 = 1.0f / (1.0f + e1);
        out[(size_t)tok * 2 + 0] = (float)i0;
        out[(size_t)tok * 2 + 1] = (float)i1;
        out[2 * T_TOK + (size_t)tok * 2 + 0] = w0;
        out[2 * T_TOK + (size_t)tok * 2 + 1] = e1 * w0;
    }
    __syncthreads();
    if (tid < E_NUM) {
        atomicAdd(&g_imp[tid],  sImp[tid]);
        atomicAdd(&g_load[tid], (float)sLoad[tid]);
    }
}

// ---------------------------------------------------------------------------
__global__ void aux_kernel(float* __restrict__ out)
{
    __shared__ float s[E_NUM];
    int t = threadIdx.x;
    s[t] = g_imp[t] * g_load[t];
    __syncthreads();
    if (t == 0) {
        float a = 0.f;
        for (int e = 0; e < E_NUM; e++) a += s[e];
        out[4 * T_TOK] = (float)E_NUM * a / ((float)T_TOK * (float)T_TOK);
    }
}

// ---------------------------------------------------------------------------
extern "C" void kernel_launch(void* const* d_in, const int* in_sizes, int n_in,
                              void* d_out, int out_size)
{
    const float* x      = (const float*)d_in[0];
    const float* rc     = (const float*)d_in[1];
    const float* gate_w = (const float*)d_in[2];
    const float* ctx_w  = (const float*)d_in[3];
    float* out = (float*)d_out;

    cudaFuncSetAttribute(router_kernel, cudaFuncAttributeMaxDynamicSharedMemorySize, SMEMSZ);

    ctx_kernel   <<<256, 256>>>(rc, ctx_w);
    router_kernel<<<128, 256, SMEMSZ>>>(x, gate_w, out);
    aux_kernel   <<<1, E_NUM>>>(out);
}

// round 10
// speedup vs baseline: 2.3351x; 1.0350x over previous
#include <cuda_runtime.h>
#include <math.h>

#define T_TOK 16384
#define C_DIM 2048
#define E_NUM 64

__device__ float g_ctx[4 * C_DIM];
__device__ float g_imp[E_NUM];
__device__ float g_load[E_NUM];

__device__ __forceinline__ void ffma2(unsigned long long& d,
                                      unsigned long long a,
                                      unsigned long long b)
{
    asm("fma.rn.f32x2 %0, %1, %2, %0;" : "+l"(d) : "l"(a), "l"(b));
}
__device__ __forceinline__ unsigned long long pack2(float v)
{
    unsigned long long r;
    unsigned int u = __float_as_uint(v);
    asm("mov.b64 %0, {%1, %1};" : "=l"(r) : "r"(u));
    return r;
}

// ---------------------------------------------------------------------------
// ctx[b][c] = sum_k rc[b][k] * ctx_w[c][k]  — bitwise-R3 fmaf/shfl chain.
// Changes vs R9 (loads only, value-safe):
//  * 16 ctx_w float4 loads pinned in flight via asm volatile (ptxas cannot
//    sink them -> MLP=16; R8/R9 showed plain batching gets sunk at 32 regs).
//  * rc (32 KB) staged once per CTA into shared; per-warp reads become LDS
//    (kills the 64 MB L2 re-read storm of 2048 warps x 32 KB).
// ---------------------------------------------------------------------------
__global__ void __launch_bounds__(256) ctx_kernel(const float* __restrict__ rc,
                                                  const float* __restrict__ ctx_w)
{
    __shared__ float src[4 * C_DIM];           // 32 KB staged rc

    if (blockIdx.x == 0 && threadIdx.x < 2 * E_NUM) {
        if (threadIdx.x < E_NUM) g_imp[threadIdx.x] = 0.f;
        else                     g_load[threadIdx.x - E_NUM] = 0.f;
    }
    // stage rc -> smem (coalesced float4)
    {
        const float4* s = (const float4*)rc;
        float4*       d = (float4*)src;
        #pragma unroll
        for (int j = 0; j < 8; j++) d[threadIdx.x + j * 256] = s[threadIdx.x + j * 256];
    }
    __syncthreads();

    const int c    = blockIdx.x * 8 + (threadIdx.x >> 5);
    const int lane = threadIdx.x & 31;
    const float4* w4 = (const float4*)(ctx_w + (size_t)c * C_DIM) + lane;

    // 16 pinned in-flight loads of ctx_w row (the DRAM stream)
    float wv[16][4];
    #pragma unroll
    for (int j = 0; j < 16; j++)
        asm volatile("ld.global.nc.v4.f32 {%0,%1,%2,%3}, [%4];"
                     : "=f"(wv[j][0]), "=f"(wv[j][1]), "=f"(wv[j][2]), "=f"(wv[j][3])
                     : "l"(w4 + j * 32));

    const float4* q0p = (const float4*)(src)             + lane;
    const float4* q1p = (const float4*)(src +     C_DIM) + lane;
    const float4* q2p = (const float4*)(src + 2 * C_DIM) + lane;
    const float4* q3p = (const float4*)(src + 3 * C_DIM) + lane;

    float a0 = 0.f, a1 = 0.f, a2 = 0.f, a3 = 0.f;
    #pragma unroll
    for (int j = 0; j < 16; j++) {
        float4 q0 = q0p[j * 32], q1 = q1p[j * 32];
        float4 q2 = q2p[j * 32], q3 = q3p[j * 32];
        a0 = fmaf(wv[j][0], q0.x, fmaf(wv[j][1], q0.y, fmaf(wv[j][2], q0.z, fmaf(wv[j][3], q0.w, a0))));
        a1 = fmaf(wv[j][0], q1.x, fmaf(wv[j][1], q1.y, fmaf(wv[j][2], q1.z, fmaf(wv[j][3], q1.w, a1))));
        a2 = fmaf(wv[j][0], q2.x, fmaf(wv[j][1], q2.y, fmaf(wv[j][2], q2.z, fmaf(wv[j][3], q2.w, a2))));
        a3 = fmaf(wv[j][0], q3.x, fmaf(wv[j][1], q3.y, fmaf(wv[j][2], q3.z, fmaf(wv[j][3], q3.w, a3))));
    }
    #pragma unroll
    for (int o = 16; o; o >>= 1) {
        a0 += __shfl_down_sync(0xffffffffu, a0, o);
        a1 += __shfl_down_sync(0xffffffffu, a1, o);
        a2 += __shfl_down_sync(0xffffffffu, a2, o);
        a3 += __shfl_down_sync(0xffffffffu, a3, o);
    }
    if (lane == 0) {
        g_ctx[c]             = a0;
        g_ctx[C_DIM + c]     = a1;
        g_ctx[2 * C_DIM + c] = a2;
        g_ctx[3 * C_DIM + c] = a3;
    }
}

// ---------------------------------------------------------------------------
// Router — UNCHANGED from the 137.3 µs R9 kernel (bitwise-R3 output).
// ---------------------------------------------------------------------------
#define OFF_XS  0
#define OFF_GS  32768
#define OFF_LOG 49152
#define OFF_IMP 82432
#define OFF_LD  82688
#define SMEMSZ  82944

__global__ void __launch_bounds__(256, 1) router_kernel(const float* __restrict__ x,
                                                        const float* __restrict__ gate_w,
                                                        float* __restrict__ out)
{
    extern __shared__ unsigned char smem[];
    float* xs2   = (float*)(smem + OFF_XS);
    float* gs2   = (float*)(smem + OFF_GS);
    float* sLog  = (float*)(smem + OFF_LOG);
    float* sImp  = (float*)(smem + OFF_IMP);
    int*   sLoad = (int*)(smem + OFF_LD);

    const int tid    = threadIdx.x;
    const int token0 = blockIdx.x * 128;
    const int batch  = token0 >> 12;

    if (tid < E_NUM) { sImp[tid] = 0.f; sLoad[tid] = 0; }

    const int lt = tid >> 1;
    const int lh = (tid & 1) << 4;
    const int ge = tid >> 2;
    const int gk = (tid & 3) << 3;
    const float4* xp = (const float4*)(x      + (size_t)(token0 + lt) * C_DIM + lh);
    const float4* cp = (const float4*)(g_ctx  + (size_t)batch         * C_DIM + lh);
    const float4* gp = (const float4*)(gate_w + (size_t)ge            * C_DIM + gk);

    const int ti = (tid & 31) << 2;
    const int ej = (tid >> 5) << 3;

    unsigned long long acc2[4][4];
    #pragma unroll
    for (int a = 0; a < 4; a++)
        #pragma unroll
        for (int b = 0; b < 4; b++) acc2[a][b] = 0ull;

    float4 xr[4], cr[4], gr[2];
    #pragma unroll
    for (int j = 0; j < 4; j++) { xr[j] = xp[j]; cr[j] = cp[j]; }
    #pragma unroll
    for (int j = 0; j < 2; j++) gr[j] = gp[j];
    {
        float* xs = xs2;
        float* gs = gs2;
        #pragma unroll
        for (int j = 0; j < 4; j++)
            #pragma unroll
            for (int i = 0; i < 4; i++)
                xs[(lh + j * 4 + i) * 128 + lt] = ((const float*)&xr[j])[i] + ((const float*)&cr[j])[i];
        #pragma unroll
        for (int j = 0; j < 2; j++)
            #pragma unroll
            for (int i = 0; i < 4; i++)
                gs[(gk + j * 4 + i) * 64 + ge] = ((const float*)&gr[j])[i];
    }
    __syncthreads();

    for (int c = 0; c < 64; c++) {
        if (c < 63) {
            #pragma unroll
            for (int j = 0; j < 4; j++) {
                xr[j] = xp[(c + 1) * 8 + j];
                cr[j] = cp[(c + 1) * 8 + j];
            }
            #pragma unroll
            for (int j = 0; j < 2; j++) gr[j] = gp[(c + 1) * 8 + j];
        }
        const float* xs = xs2 + (c & 1) * (32 * 128);
        const float* gs = gs2 + (c & 1) * (32 * 64);
        #pragma unroll
        for (int kk = 0; kk < 32; kk++) {
            float4 xv = *(const float4*)&xs[kk * 128 + ti];
            ulonglong2 gA = *(const ulonglong2*)&gs[kk * 64 + ej];
            ulonglong2 gB = *(const ulonglong2*)&gs[kk * 64 + ej + 4];
            unsigned long long xq[4] = {pack2(xv.x), pack2(xv.y), pack2(xv.z), pack2(xv.w)};
            #pragma unroll
            for (int a = 0; a < 4; a++) {
                ffma2(acc2[a][0], xq[a], gA.x);
                ffma2(acc2[a][1], xq[a], gA.y);
                ffma2(acc2[a][2], xq[a], gB.x);
                ffma2(acc2[a][3], xq[a], gB.y);
            }
        }
        if (c < 63) {
            float* xsn = xs2 + ((c + 1) & 1) * (32 * 128);
            float* gsn = gs2 + ((c + 1) & 1) * (32 * 64);
            #pragma unroll
            for (int j = 0; j < 4; j++)
                #pragma unroll
                for (int i = 0; i < 4; i++)
                    xsn[(lh + j * 4 + i) * 128 + lt] = ((const float*)&xr[j])[i] + ((const float*)&cr[j])[i];
            #pragma unroll
            for (int j = 0; j < 2; j++)
                #pragma unroll
                for (int i = 0; i < 4; i++)
                    gsn[(gk + j * 4 + i) * 64 + ge] = ((const float*)&gr[j])[i];
        }
        __syncthreads();
    }

    #pragma unroll
    for (int a = 0; a < 4; a++)
        #pragma unroll
        for (int b = 0; b < 4; b++) {
            unsigned int lo, hi;
            asm("mov.b64 {%0, %1}, %2;" : "=r"(lo), "=r"(hi) : "l"(acc2[a][b]));
            sLog[(ti + a) * 65 + ej + 2 * b]     = __uint_as_float(lo);
            sLog[(ti + a) * 65 + ej + 2 * b + 1] = __uint_as_float(hi);
        }
    __syncthreads();

    if (tid < 128) {
        const int tok = token0 + tid;
        float* row = &sLog[tid * 65];

        float v0 = -1e30f, v1 = -1e30f;
        int   i0 = 0, i1 = 0;
        for (int e = 0; e < E_NUM; e++) {
            float l = row[e];
            if (l > v0)      { v1 = v0; i1 = i0; v0 = l; i0 = e; }
            else if (l > v1) { v1 = l; i1 = e; }
        }
        float sum = 0.f;
        for (int e = 0; e < E_NUM; e++) {
            float p = expf(row[e] - v0);
            row[e] = p;
            sum += p;
        }
        float inv = 1.0f / sum;
        int lane = tid & 31;
        for (int e = 0; e < E_NUM; e++) {
            int ee = (e + lane) & 63;
            atomicAdd(&sImp[ee], row[ee] * inv);
        }
        atomicAdd(&sLoad[i0], 1);
        atomicAdd(&sLoad[i1], 1);

        float e1 = expf(v1 - v0);
        float w0 = 1.0f / (1.0f + e1);
        out[(size_t)tok * 2 + 0] = (float)i0;
        out[(size_t)tok * 2 + 1] = (float)i1;
        out[2 * T_TOK + (size_t)tok * 2 + 0] = w0;
        out[2 * T_TOK + (size_t)tok * 2 + 1] = e1 * w0;
    }
    __syncthreads();
    if (tid < E_NUM) {
        atomicAdd(&g_imp[tid],  sImp[tid]);
        atomicAdd(&g_load[tid], (float)sLoad[tid]);
    }
}

// ---------------------------------------------------------------------------
__global__ void aux_kernel(float* __restrict__ out)
{
    __shared__ float s[E_NUM];
    int t = threadIdx.x;
    s[t] = g_imp[t] * g_load[t];
    __syncthreads();
    if (t == 0) {
        float a = 0.f;
        for (int e = 0; e < E_NUM; e++) a += s[e];
        out[4 * T_TOK] = (float)E_NUM * a / ((float)T_TOK * (float)T_TOK);
    }
}

// ---------------------------------------------------------------------------
extern "C" void kernel_launch(void* const* d_in, const int* in_sizes, int n_in,
                              void* d_out, int out_size)
{
    const float* x      = (const float*)d_in[0];
    const float* rc     = (const float*)d_in[1];
    const float* gate_w = (const float*)d_in[2];
    const float* ctx_w  = (const float*)d_in[3];
    float* out = (float*)d_out;

    cudaFuncSetAttribute(router_kernel, cudaFuncAttributeMaxDynamicSharedMemorySize, SMEMSZ);

    ctx_kernel   <<<256, 256>>>(rc, ctx_w);
    router_kernel<<<128, 256, SMEMSZ>>>(x, gate_w, out);
    aux_kernel   <<<1, E_NUM>>>(out);
}

// round 11
// speedup vs baseline: 2.3613x; 1.0112x over previous
#include <cuda_runtime.h>
#include <math.h>

#define T_TOK 16384
#define C_DIM 2048
#define E_NUM 64

__device__ float g_ctx[4 * C_DIM];
__device__ float g_imp[E_NUM];
__device__ float g_load[E_NUM];
__device__ int   g_done;

__device__ __forceinline__ void ffma2(unsigned long long& d,
                                      unsigned long long a,
                                      unsigned long long b)
{
    asm("fma.rn.f32x2 %0, %1, %2, %0;" : "+l"(d) : "l"(a), "l"(b));
}
__device__ __forceinline__ unsigned long long pack2(float v)
{
    unsigned long long r;
    unsigned int u = __float_as_uint(v);
    asm("mov.b64 %0, {%1, %1};" : "=l"(r) : "r"(u));
    return r;
}

// ---------------------------------------------------------------------------
// ctx[b][c] = sum_k rc[b][k] * ctx_w[c][k]  — bitwise-R3 fmaf/shfl chain.
// vs R10: the 16 pinned ctx_w DRAM loads are issued FIRST so their ~577-cyc
// latency overlaps the rc->smem staging + barrier (previously serialized).
// ---------------------------------------------------------------------------
__global__ void __launch_bounds__(256) ctx_kernel(const float* __restrict__ rc,
                                                  const float* __restrict__ ctx_w)
{
    __shared__ float src[4 * C_DIM];           // 32 KB staged rc

    const int c    = blockIdx.x * 8 + (threadIdx.x >> 5);
    const int lane = threadIdx.x & 31;
    const float4* w4 = (const float4*)(ctx_w + (size_t)c * C_DIM) + lane;

    // 16 pinned in-flight DRAM loads (issued before anything else)
    float wv[16][4];
    #pragma unroll
    for (int j = 0; j < 16; j++)
        asm volatile("ld.global.nc.v4.f32 {%0,%1,%2,%3}, [%4];"
                     : "=f"(wv[j][0]), "=f"(wv[j][1]), "=f"(wv[j][2]), "=f"(wv[j][3])
                     : "l"(w4 + j * 32));

    if (blockIdx.x == 0 && threadIdx.x < 2 * E_NUM) {
        if (threadIdx.x < E_NUM) g_imp[threadIdx.x] = 0.f;
        else                     g_load[threadIdx.x - E_NUM] = 0.f;
        if (threadIdx.x == 0)    g_done = 0;
    }
    // stage rc -> smem (overlaps the DRAM loads above)
    {
        const float4* s = (const float4*)rc;
        float4*       d = (float4*)src;
        #pragma unroll
        for (int j = 0; j < 8; j++) d[threadIdx.x + j * 256] = s[threadIdx.x + j * 256];
    }
    __syncthreads();

    const float4* q0p = (const float4*)(src)             + lane;
    const float4* q1p = (const float4*)(src +     C_DIM) + lane;
    const float4* q2p = (const float4*)(src + 2 * C_DIM) + lane;
    const float4* q3p = (const float4*)(src + 3 * C_DIM) + lane;

    float a0 = 0.f, a1 = 0.f, a2 = 0.f, a3 = 0.f;
    #pragma unroll
    for (int j = 0; j < 16; j++) {
        float4 q0 = q0p[j * 32], q1 = q1p[j * 32];
        float4 q2 = q2p[j * 32], q3 = q3p[j * 32];
        a0 = fmaf(wv[j][0], q0.x, fmaf(wv[j][1], q0.y, fmaf(wv[j][2], q0.z, fmaf(wv[j][3], q0.w, a0))));
        a1 = fmaf(wv[j][0], q1.x, fmaf(wv[j][1], q1.y, fmaf(wv[j][2], q1.z, fmaf(wv[j][3], q1.w, a1))));
        a2 = fmaf(wv[j][0], q2.x, fmaf(wv[j][1], q2.y, fmaf(wv[j][2], q2.z, fmaf(wv[j][3], q2.w, a2))));
        a3 = fmaf(wv[j][0], q3.x, fmaf(wv[j][1], q3.y, fmaf(wv[j][2], q3.z, fmaf(wv[j][3], q3.w, a3))));
    }
    #pragma unroll
    for (int o = 16; o; o >>= 1) {
        a0 += __shfl_down_sync(0xffffffffu, a0, o);
        a1 += __shfl_down_sync(0xffffffffu, a1, o);
        a2 += __shfl_down_sync(0xffffffffu, a2, o);
        a3 += __shfl_down_sync(0xffffffffu, a3, o);
    }
    if (lane == 0) {
        g_ctx[c]             = a0;
        g_ctx[C_DIM + c]     = a1;
        g_ctx[2 * C_DIM + c] = a2;
        g_ctx[3 * C_DIM + c] = a3;
    }
}

// ---------------------------------------------------------------------------
// Router — GEMM/epilogue identical to the 132.6 µs R10 kernel (bitwise-R3).
// Added: last-CTA-done aux_loss computation (replaces the aux launch).
// ---------------------------------------------------------------------------
#define OFF_XS  0
#define OFF_GS  32768
#define OFF_LOG 49152
#define OFF_IMP 82432
#define OFF_LD  82688
#define SMEMSZ  82944

__global__ void __launch_bounds__(256, 1) router_kernel(const float* __restrict__ x,
                                                        const float* __restrict__ gate_w,
                                                        float* __restrict__ out)
{
    extern __shared__ unsigned char smem[];
    float* xs2   = (float*)(smem + OFF_XS);
    float* gs2   = (float*)(smem + OFF_GS);
    float* sLog  = (float*)(smem + OFF_LOG);
    float* sImp  = (float*)(smem + OFF_IMP);
    int*   sLoad = (int*)(smem + OFF_LD);

    const int tid    = threadIdx.x;
    const int token0 = blockIdx.x * 128;
    const int batch  = token0 >> 12;

    if (tid < E_NUM) { sImp[tid] = 0.f; sLoad[tid] = 0; }

    const int lt = tid >> 1;
    const int lh = (tid & 1) << 4;
    const int ge = tid >> 2;
    const int gk = (tid & 3) << 3;
    const float4* xp = (const float4*)(x      + (size_t)(token0 + lt) * C_DIM + lh);
    const float4* cp = (const float4*)(g_ctx  + (size_t)batch         * C_DIM + lh);
    const float4* gp = (const float4*)(gate_w + (size_t)ge            * C_DIM + gk);

    const int ti = (tid & 31) << 2;
    const int ej = (tid >> 5) << 3;

    unsigned long long acc2[4][4];
    #pragma unroll
    for (int a = 0; a < 4; a++)
        #pragma unroll
        for (int b = 0; b < 4; b++) acc2[a][b] = 0ull;

    float4 xr[4], cr[4], gr[2];
    #pragma unroll
    for (int j = 0; j < 4; j++) { xr[j] = xp[j]; cr[j] = cp[j]; }
    #pragma unroll
    for (int j = 0; j < 2; j++) gr[j] = gp[j];
    {
        float* xs = xs2;
        float* gs = gs2;
        #pragma unroll
        for (int j = 0; j < 4; j++)
            #pragma unroll
            for (int i = 0; i < 4; i++)
                xs[(lh + j * 4 + i) * 128 + lt] = ((const float*)&xr[j])[i] + ((const float*)&cr[j])[i];
        #pragma unroll
        for (int j = 0; j < 2; j++)
            #pragma unroll
            for (int i = 0; i < 4; i++)
                gs[(gk + j * 4 + i) * 64 + ge] = ((const float*)&gr[j])[i];
    }
    __syncthreads();

    for (int c = 0; c < 64; c++) {
        if (c < 63) {
            #pragma unroll
            for (int j = 0; j < 4; j++) {
                xr[j] = xp[(c + 1) * 8 + j];
                cr[j] = cp[(c + 1) * 8 + j];
            }
            #pragma unroll
            for (int j = 0; j < 2; j++) gr[j] = gp[(c + 1) * 8 + j];
        }
        const float* xs = xs2 + (c & 1) * (32 * 128);
        const float* gs = gs2 + (c & 1) * (32 * 64);
        #pragma unroll
        for (int kk = 0; kk < 32; kk++) {
            float4 xv = *(const float4*)&xs[kk * 128 + ti];
            ulonglong2 gA = *(const ulonglong2*)&gs[kk * 64 + ej];
            ulonglong2 gB = *(const ulonglong2*)&gs[kk * 64 + ej + 4];
            unsigned long long xq[4] = {pack2(xv.x), pack2(xv.y), pack2(xv.z), pack2(xv.w)};
            #pragma unroll
            for (int a = 0; a < 4; a++) {
                ffma2(acc2[a][0], xq[a], gA.x);
                ffma2(acc2[a][1], xq[a], gA.y);
                ffma2(acc2[a][2], xq[a], gB.x);
                ffma2(acc2[a][3], xq[a], gB.y);
            }
        }
        if (c < 63) {
            float* xsn = xs2 + ((c + 1) & 1) * (32 * 128);
            float* gsn = gs2 + ((c + 1) & 1) * (32 * 64);
            #pragma unroll
            for (int j = 0; j < 4; j++)
                #pragma unroll
                for (int i = 0; i < 4; i++)
                    xsn[(lh + j * 4 + i) * 128 + lt] = ((const float*)&xr[j])[i] + ((const float*)&cr[j])[i];
            #pragma unroll
            for (int j = 0; j < 2; j++)
                #pragma unroll
                for (int i = 0; i < 4; i++)
                    gsn[(gk + j * 4 + i) * 64 + ge] = ((const float*)&gr[j])[i];
        }
        __syncthreads();
    }

    #pragma unroll
    for (int a = 0; a < 4; a++)
        #pragma unroll
        for (int b = 0; b < 4; b++) {
            unsigned int lo, hi;
            asm("mov.b64 {%0, %1}, %2;" : "=r"(lo), "=r"(hi) : "l"(acc2[a][b]));
            sLog[(ti + a) * 65 + ej + 2 * b]     = __uint_as_float(lo);
            sLog[(ti + a) * 65 + ej + 2 * b + 1] = __uint_as_float(hi);
        }
    __syncthreads();

    if (tid < 128) {
        const int tok = token0 + tid;
        float* row = &sLog[tid * 65];

        float v0 = -1e30f, v1 = -1e30f;
        int   i0 = 0, i1 = 0;
        for (int e = 0; e < E_NUM; e++) {
            float l = row[e];
            if (l > v0)      { v1 = v0; i1 = i0; v0 = l; i0 = e; }
            else if (l > v1) { v1 = l; i1 = e; }
        }
        float sum = 0.f;
        for (int e = 0; e < E_NUM; e++) {
            float p = expf(row[e] - v0);
            row[e] = p;
            sum += p;
        }
        float inv = 1.0f / sum;
        int lane = tid & 31;
        for (int e = 0; e < E_NUM; e++) {
            int ee = (e + lane) & 63;
            atomicAdd(&sImp[ee], row[ee] * inv);
        }
        atomicAdd(&sLoad[i0], 1);
        atomicAdd(&sLoad[i1], 1);

        float e1 = expf(v1 - v0);
        float w0 = 1.0f / (1.0f + e1);
        out[(size_t)tok * 2 + 0] = (float)i0;
        out[(size_t)tok * 2 + 1] = (float)i1;
        out[2 * T_TOK + (size_t)tok * 2 + 0] = w0;
        out[2 * T_TOK + (size_t)tok * 2 + 1] = e1 * w0;
    }
    __syncthreads();
    if (tid < E_NUM) {
        atomicAdd(&g_imp[tid],  sImp[tid]);
        atomicAdd(&g_load[tid], (float)sLoad[tid]);
    }

    // ---- last CTA computes aux_loss (replaces the aux launch) ----
    __shared__ int sLast;
    __syncthreads();
    if (tid == 0) {
        __threadfence();
        sLast = (atomicAdd(&g_done, 1) == (int)gridDim.x - 1) ? 1 : 0;
    }
    __syncthreads();
    if (sLast && tid == 0) {
        float a = 0.f;
        for (int e = 0; e < E_NUM; e++) {
            float im = atomicAdd(&g_imp[e],  0.f);   // ordered reads
            float ld = atomicAdd(&g_load[e], 0.f);
            a += im * ld;
        }
        out[4 * T_TOK] = (float)E_NUM * a / ((float)T_TOK * (float)T_TOK);
    }
}

// ---------------------------------------------------------------------------
extern "C" void kernel_launch(void* const* d_in, const int* in_sizes, int n_in,
                              void* d_out, int out_size)
{
    const float* x      = (const float*)d_in[0];
    const float* rc     = (const float*)d_in[1];
    const float* gate_w = (const float*)d_in[2];
    const float* ctx_w  = (const float*)d_in[3];
    float* out = (float*)d_out;

    cudaFuncSetAttribute(router_kernel, cudaFuncAttributeMaxDynamicSharedMemorySize, SMEMSZ);

    ctx_kernel   <<<256, 256>>>(rc, ctx_w);
    router_kernel<<<128, 256, SMEMSZ>>>(x, gate_w, out);
}